// round 9
// baseline (speedup 1.0000x reference)
#include <cuda_runtime.h>
#include <cuda_fp16.h>
#include <cstdint>

#define N_NODES 100000
#define F_IN    512
#define F_HID   256
#define F_OUT   40
#define E_MAX   3200000

#define SCAN_B  512
#define SCAN_NB ((N_NODES + SCAN_B - 1) / SCAN_B)   // 196

// ---------------- scratch (device globals; no allocation allowed) ----------
__device__ __align__(128) __half g_s1h[(size_t)N_NODES * F_HID];   // 51.2 MB
__device__ __align__(128) __half g_s2h[(size_t)N_NODES * F_OUT];   // 8 MB

// W1 pre-packed into mma B-fragment order: [kt(32)][nt(32)][lane(32)][2]
__device__ __align__(16) uint32_t g_w1f[32 * 32 * 32 * 2];          // 256 KB
// W2 pre-packed fragments: [kt(16)][nt(5)][lane(32)][2]
__device__ __align__(16) uint32_t g_w2f[16 * 5 * 32 * 2];           // 10 KB

__device__ int  g_cnt[N_NODES];
__device__ int  g_off[N_NODES];
__device__ int  g_pos[N_NODES];
__device__ int  g_blksum[SCAN_NB];
__device__ __align__(16) int2 g_csr[E_MAX];    // (src, float-bits of w)

// ---------------- fp16 mma helper -------------------------------------------
__device__ __forceinline__ void mma_f16(float* c, const uint32_t* a, const uint32_t* b) {
    asm volatile("mma.sync.aligned.m16n8k16.row.col.f32.f16.f16.f32 "
                 "{%0,%1,%2,%3}, {%4,%5,%6,%7}, {%8,%9}, {%0,%1,%2,%3};"
                 : "+f"(c[0]), "+f"(c[1]), "+f"(c[2]), "+f"(c[3])
                 : "r"(a[0]), "r"(a[1]), "r"(a[2]), "r"(a[3]),
                   "r"(b[0]), "r"(b[1]));
}

// ================ pack W1 (fp32 [512,256]) into fragment order ===============
__global__ void pack_W1(const float* __restrict__ W1) {
    const int idx = blockIdx.x * blockDim.x + threadIdx.x;   // 0..32767
    if (idx >= 32 * 32 * 32) return;
    const int kt = idx >> 10;
    const int rem = idx & 1023;
    const int nt = rem >> 5;
    const int ln = rem & 31;
    const int n = nt * 8 + (ln >> 2);
    const int k = kt * 16 + (ln & 3) * 2;
    const __half2 h0 = __floats2half2_rn(W1[(size_t)k * F_HID + n],
                                         W1[(size_t)(k + 1) * F_HID + n]);
    const __half2 h1 = __floats2half2_rn(W1[(size_t)(k + 8) * F_HID + n],
                                         W1[(size_t)(k + 9) * F_HID + n]);
    g_w1f[idx * 2]     = *(const uint32_t*)&h0;
    g_w1f[idx * 2 + 1] = *(const uint32_t*)&h1;
}

// ================ pack W2 (fp32 [256,40]) into fragment order ================
__global__ void pack_W2(const float* __restrict__ W2) {
    const int idx = blockIdx.x * blockDim.x + threadIdx.x;   // 0..2559
    if (idx >= 16 * 5 * 32) return;
    const int kt = idx / (5 * 32);
    const int rem = idx % (5 * 32);
    const int nt = rem / 32;
    const int ln = rem % 32;
    const int n = nt * 8 + (ln >> 2);
    const int k0 = kt * 16 + (ln & 3) * 2;
    const __half2 h0 = __floats2half2_rn(W2[(size_t)k0 * F_OUT + n],
                                         W2[(size_t)(k0 + 1) * F_OUT + n]);
    const __half2 h1 = __floats2half2_rn(W2[(size_t)(k0 + 8) * F_OUT + n],
                                         W2[(size_t)(k0 + 9) * F_OUT + n]);
    g_w2f[idx * 2]     = *(const uint32_t*)&h0;
    g_w2f[idx * 2 + 1] = *(const uint32_t*)&h1;
}

// ================= gemm1: support1 = x @ W1  (fp16 MMA, fp16 out) ==========
#define G1_BM 128
#define G1_BK 32
#define AS_PAD 36

__global__ __launch_bounds__(256, 1) void gemm1_f16(const float* __restrict__ A, int M) {
    __shared__ __align__(16) uint32_t As[2][8][8][AS_PAD];   // 18.4 KB

    const int tid  = threadIdx.x;
    const int lane = tid & 31;
    const int warp = tid >> 5;
    const int wm = warp & 1;
    const int wn = warp >> 1;
    const int rowBase = blockIdx.x * G1_BM;

    const int ar  = tid >> 1;
    const int aks = tid & 1;
    const int amt = ar >> 4, arr = ar & 15;
    const int b0  = arr >> 3;
    const int l0  = (arr & 7) * 4;

    float acc[4][8][4];
    #pragma unroll
    for (int mt = 0; mt < 4; mt++)
        #pragma unroll
        for (int nt = 0; nt < 8; nt++)
            #pragma unroll
            for (int r = 0; r < 4; r++) acc[mt][nt][r] = 0.f;

    const int arow = rowBase + ar;
    const float* Arow = A + (size_t)arow * F_IN + aks * 16;
    float4 pa[4];

    {
        #pragma unroll
        for (int j = 0; j < 4; j++)
            pa[j] = (arow < M) ? __ldcs((const float4*)(Arow + 4 * j))
                               : make_float4(0.f, 0.f, 0.f, 0.f);
        const float* f = (const float*)pa;
        uint4 lo, hi;
        uint32_t* plo = (uint32_t*)&lo;
        uint32_t* phi = (uint32_t*)&hi;
        #pragma unroll
        for (int p = 0; p < 4; p++) {
            const __half2 a = __floats2half2_rn(f[2 * p],     f[2 * p + 1]);
            const __half2 b = __floats2half2_rn(f[8 + 2 * p], f[9 + 2 * p]);
            plo[p] = *(const uint32_t*)&a;
            phi[p] = *(const uint32_t*)&b;
        }
        *(uint4*)&As[0][amt][aks * 4 + b0][l0]     = lo;
        *(uint4*)&As[0][amt][aks * 4 + b0 + 2][l0] = hi;
    }
    __syncthreads();

    const int NT = F_IN / G1_BK;   // 16
    for (int t = 0; t < NT; t++) {
        const int buf = t & 1;
        if (t + 1 < NT) {
            const float* Anext = Arow + (t + 1) * G1_BK;
            #pragma unroll
            for (int j = 0; j < 4; j++)
                pa[j] = (arow < M) ? __ldcs((const float4*)(Anext + 4 * j))
                                   : make_float4(0.f, 0.f, 0.f, 0.f);
        }

        #pragma unroll
        for (int ks = 0; ks < 2; ks++) {
            const int kt = t * 2 + ks;
            uint32_t bfr[8][2];
            #pragma unroll
            for (int nt = 0; nt < 8; nt++) {
                const uint2 v = __ldg((const uint2*)
                    &g_w1f[(((size_t)kt * 32 + wn * 8 + nt) * 32 + lane) * 2]);
                bfr[nt][0] = v.x; bfr[nt][1] = v.y;
            }
            uint32_t afr[4][4];
            #pragma unroll
            for (int mt = 0; mt < 4; mt++)
                #pragma unroll
                for (int r = 0; r < 4; r++)
                    afr[mt][r] = As[buf][wm * 4 + mt][ks * 4 + r][lane];
            #pragma unroll
            for (int mt = 0; mt < 4; mt++)
                #pragma unroll
                for (int nt = 0; nt < 8; nt++)
                    mma_f16(acc[mt][nt], afr[mt], bfr[nt]);
        }

        if (t + 1 < NT) {
            const int nb = buf ^ 1;
            const float* f = (const float*)pa;
            uint4 lo, hi;
            uint32_t* plo = (uint32_t*)&lo;
            uint32_t* phi = (uint32_t*)&hi;
            #pragma unroll
            for (int p = 0; p < 4; p++) {
                const __half2 a = __floats2half2_rn(f[2 * p],     f[2 * p + 1]);
                const __half2 b = __floats2half2_rn(f[8 + 2 * p], f[9 + 2 * p]);
                plo[p] = *(const uint32_t*)&a;
                phi[p] = *(const uint32_t*)&b;
            }
            *(uint4*)&As[nb][amt][aks * 4 + b0][l0]     = lo;
            *(uint4*)&As[nb][amt][aks * 4 + b0 + 2][l0] = hi;
        }
        __syncthreads();
    }

    #pragma unroll
    for (int mt = 0; mt < 4; mt++) {
        const int row0 = rowBase + wm * 64 + mt * 16 + (lane >> 2);
        #pragma unroll
        for (int nt = 0; nt < 8; nt++) {
            const int col = wn * 64 + nt * 8 + (lane & 3) * 2;
            if (row0 < M)
                *(__half2*)(g_s1h + (size_t)row0 * F_HID + col) =
                    __floats2half2_rn(acc[mt][nt][0], acc[mt][nt][1]);
            if (row0 + 8 < M)
                *(__half2*)(g_s1h + (size_t)(row0 + 8) * F_HID + col) =
                    __floats2half2_rn(acc[mt][nt][2], acc[mt][nt][3]);
        }
    }
}

// ================= CSR build =================================================
__global__ void zero_cnt() {
    const int i = blockIdx.x * blockDim.x + threadIdx.x;
    if (i < N_NODES) g_cnt[i] = 0;
}

__global__ void hist_dst(const int* __restrict__ dst, int E) {
    const int e = blockIdx.x * blockDim.x + threadIdx.x;
    if (e < E) atomicAdd(&g_cnt[__ldcs(dst + e)], 1);
}

__global__ void scan_block() {
    __shared__ int sh[SCAN_B];
    const int t = threadIdx.x;
    const int i = blockIdx.x * SCAN_B + t;
    const int v = (i < N_NODES) ? g_cnt[i] : 0;
    sh[t] = v;
    __syncthreads();
    #pragma unroll
    for (int o = 1; o < SCAN_B; o <<= 1) {
        int x = 0;
        if (t >= o) x = sh[t - o];
        __syncthreads();
        sh[t] += x;
        __syncthreads();
    }
    if (i < N_NODES) g_off[i] = sh[t] - v;
    if (t == SCAN_B - 1) g_blksum[blockIdx.x] = sh[t];
}

__global__ void scan_top() {
    __shared__ int sh[256];
    const int t = threadIdx.x;
    const int v = (t < SCAN_NB) ? g_blksum[t] : 0;
    sh[t] = v;
    __syncthreads();
    #pragma unroll
    for (int o = 1; o < 256; o <<= 1) {
        int x = 0;
        if (t >= o) x = sh[t - o];
        __syncthreads();
        sh[t] += x;
        __syncthreads();
    }
    if (t < SCAN_NB) g_blksum[t] = sh[t] - v;
}

__global__ void scan_add() {
    const int i = blockIdx.x * blockDim.x + threadIdx.x;
    if (i < N_NODES) {
        const int o = g_off[i] + g_blksum[i / SCAN_B];
        g_off[i] = o;
        g_pos[i] = o;
    }
}

__global__ void fill_csr(const int* __restrict__ src, const int* __restrict__ dst,
                         const float* __restrict__ ew, int E) {
    const int e = blockIdx.x * blockDim.x + threadIdx.x;
    if (e < E) {
        const int p = atomicAdd(&g_pos[__ldcs(dst + e)], 1);
        __stcs(&g_csr[p], make_int2(__ldcs(src + e), __float_as_int(__ldcs(ew + e))));
    }
}

// ===== fused layer-1 gather + relu + gemm2: 16 nodes per 512-thread block ====
// Phase 1: warp w gathers node (block*16+w), relu, fp16-pack -> smem row.
// Phase 2: warps 0..4 run m16n8k16 mma over the 16x256 smem tile (one n-tile
//          of W2 each) and write s2h. h1 never touches gmem.
#define AH_STRIDE 132   // uint32 words per row (128 + 4 pad -> conflict-free)

__device__ __forceinline__ void accum8(float* acc, uint4 v, float w) {
    const __half2* h = (const __half2*)&v;
    #pragma unroll
    for (int j = 0; j < 4; j++) {
        const float2 f = __half22float2(h[j]);
        acc[2 * j]     = fmaf(w, f.x, acc[2 * j]);
        acc[2 * j + 1] = fmaf(w, f.y, acc[2 * j + 1]);
    }
}

__global__ __launch_bounds__(512) void gather1_gemm2(const float* __restrict__ b1) {
    __shared__ __align__(16) uint32_t Ah[16][AH_STRIDE];   // 8.4 KB

    const int tid  = threadIdx.x;
    const int warp = tid >> 5;
    const int lane = tid & 31;
    const int n = blockIdx.x * 16 + warp;    // grid = 6250 exactly

    // ---- phase 1: gather ----
    {
        const int beg = g_off[n];
        const int end = beg + g_cnt[n];

        float acc[8];
        {
            const float4 blo = __ldg((const float4*)b1 + lane * 2);
            const float4 bhi = __ldg((const float4*)b1 + lane * 2 + 1);
            acc[0] = blo.x; acc[1] = blo.y; acc[2] = blo.z; acc[3] = blo.w;
            acc[4] = bhi.x; acc[5] = bhi.y; acc[6] = bhi.z; acc[7] = bhi.w;
        }

        int e = beg;
        for (; e + 7 < end; e += 8) {
            int2 c[8];
            uint4 v[8];
            #pragma unroll
            for (int i = 0; i < 8; i++) c[i] = __ldcs(&g_csr[e + i]);
            #pragma unroll
            for (int i = 0; i < 8; i++)
                v[i] = __ldg((const uint4*)(g_s1h + (size_t)c[i].x * F_HID) + lane);
            #pragma unroll
            for (int i = 0; i < 8; i++) accum8(acc, v[i], __int_as_float(c[i].y));
        }
        for (; e < end; e++) {
            const int2 c = __ldcs(&g_csr[e]);
            const uint4 v = __ldg((const uint4*)(g_s1h + (size_t)c.x * F_HID) + lane);
            accum8(acc, v, __int_as_float(c.y));
        }

        uint4 o;
        __half2* ph = (__half2*)&o;
        #pragma unroll
        for (int j = 0; j < 4; j++)
            ph[j] = __floats2half2_rn(fmaxf(acc[2 * j], 0.f), fmaxf(acc[2 * j + 1], 0.f));
        *(uint4*)&Ah[warp][lane * 4] = o;
    }
    __syncthreads();

    // ---- phase 2: 16x40 gemm via mma (warps 0..4, one n-tile each) ----
    if (warp < 5) {
        const int nt = warp;
        float acc[4] = {0.f, 0.f, 0.f, 0.f};
        const int m = lane >> 2;          // 0..7
        const int kq = lane & 3;          // k-quad

        #pragma unroll
        for (int kt = 0; kt < 16; kt++) {
            uint32_t a[4];
            a[0] = Ah[m][kt * 8 + kq];
            a[1] = Ah[m + 8][kt * 8 + kq];
            a[2] = Ah[m][kt * 8 + 4 + kq];
            a[3] = Ah[m + 8][kt * 8 + 4 + kq];
            const uint2 bv = __ldg((const uint2*)
                &g_w2f[(((size_t)kt * 5 + nt) * 32 + lane) * 2]);
            const uint32_t b[2] = {bv.x, bv.y};
            mma_f16(acc, a, b);
        }

        const int node0 = blockIdx.x * 16 + m;
        const int col = nt * 8 + (lane & 3) * 2;
        *(__half2*)(g_s2h + (size_t)node0 * F_OUT + col) =
            __floats2half2_rn(acc[0], acc[1]);
        *(__half2*)(g_s2h + (size_t)(node0 + 8) * F_OUT + col) =
            __floats2half2_rn(acc[2], acc[3]);
    }
}

// ========== layer-2 gather fused with log_softmax: warp per node ============
__global__ __launch_bounds__(256) void gather2_softmax(const float* __restrict__ b2,
                                                       float* __restrict__ out) {
    const int n = (blockIdx.x * blockDim.x + threadIdx.x) >> 5;
    const int lane = threadIdx.x & 31;
    if (n >= N_NODES) return;
    const int beg = g_off[n];
    const int end = beg + g_cnt[n];
    const bool act = lane < (F_OUT / 2);

    float accA = 0.f, accB = 0.f;
    if (act) {
        const float2 b = __ldg((const float2*)b2 + lane);
        accA = b.x; accB = b.y;
    }

    int e = beg;
    for (; e + 1 < end; e += 2) {
        const int2 c0 = __ldcs(&g_csr[e]);
        const int2 c1 = __ldcs(&g_csr[e + 1]);
        if (act) {
            const __half2 v0 = __ldg((const __half2*)(g_s2h + (size_t)c0.x * F_OUT) + lane);
            const __half2 v1 = __ldg((const __half2*)(g_s2h + (size_t)c1.x * F_OUT) + lane);
            const float w0 = __int_as_float(c0.y);
            const float w1 = __int_as_float(c1.y);
            const float2 f0 = __half22float2(v0);
            const float2 f1 = __half22float2(v1);
            accA = fmaf(w0, f0.x, accA); accB = fmaf(w0, f0.y, accB);
            accA = fmaf(w1, f1.x, accA); accB = fmaf(w1, f1.y, accB);
        }
    }
    if (e < end) {
        const int2 c = __ldcs(&g_csr[e]);
        if (act) {
            const __half2 v = __ldg((const __half2*)(g_s2h + (size_t)c.x * F_OUT) + lane);
            const float w = __int_as_float(c.y);
            const float2 f = __half22float2(v);
            accA = fmaf(w, f.x, accA); accB = fmaf(w, f.y, accB);
        }
    }

    const float NEG_INF = __int_as_float(0xff800000);
    float m = act ? fmaxf(accA, accB) : NEG_INF;
    #pragma unroll
    for (int o = 16; o > 0; o >>= 1)
        m = fmaxf(m, __shfl_xor_sync(0xffffffffu, m, o));
    float s = act ? (expf(accA - m) + expf(accB - m)) : 0.f;
    #pragma unroll
    for (int o = 16; o > 0; o >>= 1)
        s += __shfl_xor_sync(0xffffffffu, s, o);
    const float l = m + logf(s);

    if (act)
        *((float2*)(out + (size_t)n * F_OUT) + lane) = make_float2(accA - l, accB - l);
}

// ---------------- launch ----------------------------------------------------
extern "C" void kernel_launch(void* const* d_in, const int* in_sizes, int n_in,
                              void* d_out, int out_size) {
    const float* x   = (const float*)d_in[0];
    const int*   ei  = (const int*)d_in[1];
    const float* ew  = (const float*)d_in[2];
    const float* W1  = (const float*)d_in[3];
    const float* b1  = (const float*)d_in[4];
    const float* W2  = (const float*)d_in[5];
    const float* b2  = (const float*)d_in[6];
    float* out = (float*)d_out;

    const int E = in_sizes[2];
    const int* src = ei;
    const int* dst = ei + E;

    // Fork: CSR build + W2 pack run concurrently with W1 pack + gemm1.
    cudaStream_t s2;
    cudaStreamCreate(&s2);
    cudaEvent_t evFork, evJoin;
    cudaEventCreateWithFlags(&evFork, cudaEventDisableTiming);
    cudaEventCreateWithFlags(&evJoin, cudaEventDisableTiming);

    cudaEventRecord(evFork, 0);
    cudaStreamWaitEvent(s2, evFork, 0);

    // branch A (main stream): pack W1, then support1 = x @ W1
    pack_W1<<<128, 256>>>(W1);
    gemm1_f16<<<(N_NODES + G1_BM - 1) / G1_BM, 256>>>(x, N_NODES);

    // branch B (side stream): W2 pack + CSR build
    {
        const int nb = (N_NODES + 255) / 256;
        const int eb = (E + 255) / 256;
        pack_W2<<<10, 256, 0, s2>>>(W2);
        zero_cnt<<<nb, 256, 0, s2>>>();
        hist_dst<<<eb, 256, 0, s2>>>(dst, E);
        scan_block<<<SCAN_NB, SCAN_B, 0, s2>>>();
        scan_top<<<1, 256, 0, s2>>>();
        scan_add<<<nb, 256, 0, s2>>>();
        fill_csr<<<eb, 256, 0, s2>>>(src, dst, ew, E);
    }

    cudaEventRecord(evJoin, s2);
    cudaStreamWaitEvent(0, evJoin, 0);

    // fused layer-1 gather + relu + gemm2 (h1 never leaves the SM)
    gather1_gemm2<<<N_NODES / 16, 512>>>(b1);
    // out = log_softmax(b2 + gather(ew * support2[src]))
    gather2_softmax<<<(N_NODES * 32 + 255) / 256, 256>>>(b2, out);

    cudaStreamDestroy(s2);
    cudaEventDestroy(evFork);
    cudaEventDestroy(evJoin);
}

// round 10
// speedup vs baseline: 1.0056x; 1.0056x over previous
#include <cuda_runtime.h>
#include <cuda_fp16.h>
#include <cstdint>

#define N_NODES 100000
#define F_IN    512
#define F_HID   256
#define F_OUT   40
#define E_MAX   3200000

#define SCAN_B  512
#define SCAN_NB ((N_NODES + SCAN_B - 1) / SCAN_B)   // 196

// split point for the gather1->gemm2 pipeline (multiple of 128)
#define N_LO 50048
#define N_HI (N_NODES - N_LO)

// ---------------- scratch (device globals; no allocation allowed) ----------
__device__ __align__(128) __half g_s1h[(size_t)N_NODES * F_HID];   // 51.2 MB
__device__ __align__(128) __half g_h1h[(size_t)N_NODES * F_HID];   // 51.2 MB
__device__ __align__(128) __half g_s2h[(size_t)N_NODES * F_OUT];   // 8 MB

// W1 pre-packed into mma B-fragment order: [kt(32)][nt(32)][lane(32)][2]
__device__ __align__(16) uint32_t g_w1f[32 * 32 * 32 * 2];          // 256 KB
// W2 pre-packed fragments: [kt(16)][nt(5)][lane(32)][2]
__device__ __align__(16) uint32_t g_w2f[16 * 5 * 32 * 2];           // 10 KB

__device__ int  g_cnt[N_NODES];
__device__ int  g_off[N_NODES];
__device__ int  g_pos[N_NODES];
__device__ int  g_blksum[SCAN_NB];
__device__ __align__(16) int2 g_csr[E_MAX];    // (src, float-bits of w)

// ---------------- fp16 mma helper -------------------------------------------
__device__ __forceinline__ void mma_f16(float* c, const uint32_t* a, const uint32_t* b) {
    asm volatile("mma.sync.aligned.m16n8k16.row.col.f32.f16.f16.f32 "
                 "{%0,%1,%2,%3}, {%4,%5,%6,%7}, {%8,%9}, {%0,%1,%2,%3};"
                 : "+f"(c[0]), "+f"(c[1]), "+f"(c[2]), "+f"(c[3])
                 : "r"(a[0]), "r"(a[1]), "r"(a[2]), "r"(a[3]),
                   "r"(b[0]), "r"(b[1]));
}

// ================ pack W1 (fp32 [512,256]) into fragment order ===============
__global__ void pack_W1(const float* __restrict__ W1) {
    const int idx = blockIdx.x * blockDim.x + threadIdx.x;   // 0..32767
    if (idx >= 32 * 32 * 32) return;
    const int kt = idx >> 10;
    const int rem = idx & 1023;
    const int nt = rem >> 5;
    const int ln = rem & 31;
    const int n = nt * 8 + (ln >> 2);
    const int k = kt * 16 + (ln & 3) * 2;
    const __half2 h0 = __floats2half2_rn(W1[(size_t)k * F_HID + n],
                                         W1[(size_t)(k + 1) * F_HID + n]);
    const __half2 h1 = __floats2half2_rn(W1[(size_t)(k + 8) * F_HID + n],
                                         W1[(size_t)(k + 9) * F_HID + n]);
    g_w1f[idx * 2]     = *(const uint32_t*)&h0;
    g_w1f[idx * 2 + 1] = *(const uint32_t*)&h1;
}

// ================ pack W2 (fp32 [256,40]) into fragment order ================
__global__ void pack_W2(const float* __restrict__ W2) {
    const int idx = blockIdx.x * blockDim.x + threadIdx.x;   // 0..2559
    if (idx >= 16 * 5 * 32) return;
    const int kt = idx / (5 * 32);
    const int rem = idx % (5 * 32);
    const int nt = rem / 32;
    const int ln = rem % 32;
    const int n = nt * 8 + (ln >> 2);
    const int k0 = kt * 16 + (ln & 3) * 2;
    const __half2 h0 = __floats2half2_rn(W2[(size_t)k0 * F_OUT + n],
                                         W2[(size_t)(k0 + 1) * F_OUT + n]);
    const __half2 h1 = __floats2half2_rn(W2[(size_t)(k0 + 8) * F_OUT + n],
                                         W2[(size_t)(k0 + 9) * F_OUT + n]);
    g_w2f[idx * 2]     = *(const uint32_t*)&h0;
    g_w2f[idx * 2 + 1] = *(const uint32_t*)&h1;
}

// ================= gemm1: support1 = x @ W1  (fp16 MMA, fp16 out) ==========
#define G1_BM 128
#define G1_BK 32
#define AS_PAD 36

__global__ __launch_bounds__(256, 1) void gemm1_f16(const float* __restrict__ A, int M) {
    __shared__ __align__(16) uint32_t As[2][8][8][AS_PAD];   // 18.4 KB

    const int tid  = threadIdx.x;
    const int lane = tid & 31;
    const int warp = tid >> 5;
    const int wm = warp & 1;
    const int wn = warp >> 1;
    const int rowBase = blockIdx.x * G1_BM;

    const int ar  = tid >> 1;
    const int aks = tid & 1;
    const int amt = ar >> 4, arr = ar & 15;
    const int b0  = arr >> 3;
    const int l0  = (arr & 7) * 4;

    float acc[4][8][4];
    #pragma unroll
    for (int mt = 0; mt < 4; mt++)
        #pragma unroll
        for (int nt = 0; nt < 8; nt++)
            #pragma unroll
            for (int r = 0; r < 4; r++) acc[mt][nt][r] = 0.f;

    const int arow = rowBase + ar;
    const float* Arow = A + (size_t)arow * F_IN + aks * 16;
    float4 pa[4];

    {
        #pragma unroll
        for (int j = 0; j < 4; j++)
            pa[j] = (arow < M) ? __ldcs((const float4*)(Arow + 4 * j))
                               : make_float4(0.f, 0.f, 0.f, 0.f);
        const float* f = (const float*)pa;
        uint4 lo, hi;
        uint32_t* plo = (uint32_t*)&lo;
        uint32_t* phi = (uint32_t*)&hi;
        #pragma unroll
        for (int p = 0; p < 4; p++) {
            const __half2 a = __floats2half2_rn(f[2 * p],     f[2 * p + 1]);
            const __half2 b = __floats2half2_rn(f[8 + 2 * p], f[9 + 2 * p]);
            plo[p] = *(const uint32_t*)&a;
            phi[p] = *(const uint32_t*)&b;
        }
        *(uint4*)&As[0][amt][aks * 4 + b0][l0]     = lo;
        *(uint4*)&As[0][amt][aks * 4 + b0 + 2][l0] = hi;
    }
    __syncthreads();

    const int NT = F_IN / G1_BK;   // 16
    for (int t = 0; t < NT; t++) {
        const int buf = t & 1;
        if (t + 1 < NT) {
            const float* Anext = Arow + (t + 1) * G1_BK;
            #pragma unroll
            for (int j = 0; j < 4; j++)
                pa[j] = (arow < M) ? __ldcs((const float4*)(Anext + 4 * j))
                                   : make_float4(0.f, 0.f, 0.f, 0.f);
        }

        #pragma unroll
        for (int ks = 0; ks < 2; ks++) {
            const int kt = t * 2 + ks;
            uint32_t bfr[8][2];
            #pragma unroll
            for (int nt = 0; nt < 8; nt++) {
                const uint2 v = __ldg((const uint2*)
                    &g_w1f[(((size_t)kt * 32 + wn * 8 + nt) * 32 + lane) * 2]);
                bfr[nt][0] = v.x; bfr[nt][1] = v.y;
            }
            uint32_t afr[4][4];
            #pragma unroll
            for (int mt = 0; mt < 4; mt++)
                #pragma unroll
                for (int r = 0; r < 4; r++)
                    afr[mt][r] = As[buf][wm * 4 + mt][ks * 4 + r][lane];
            #pragma unroll
            for (int mt = 0; mt < 4; mt++)
                #pragma unroll
                for (int nt = 0; nt < 8; nt++)
                    mma_f16(acc[mt][nt], afr[mt], bfr[nt]);
        }

        if (t + 1 < NT) {
            const int nb = buf ^ 1;
            const float* f = (const float*)pa;
            uint4 lo, hi;
            uint32_t* plo = (uint32_t*)&lo;
            uint32_t* phi = (uint32_t*)&hi;
            #pragma unroll
            for (int p = 0; p < 4; p++) {
                const __half2 a = __floats2half2_rn(f[2 * p],     f[2 * p + 1]);
                const __half2 b = __floats2half2_rn(f[8 + 2 * p], f[9 + 2 * p]);
                plo[p] = *(const uint32_t*)&a;
                phi[p] = *(const uint32_t*)&b;
            }
            *(uint4*)&As[nb][amt][aks * 4 + b0][l0]     = lo;
            *(uint4*)&As[nb][amt][aks * 4 + b0 + 2][l0] = hi;
        }
        __syncthreads();
    }

    #pragma unroll
    for (int mt = 0; mt < 4; mt++) {
        const int row0 = rowBase + wm * 64 + mt * 16 + (lane >> 2);
        #pragma unroll
        for (int nt = 0; nt < 8; nt++) {
            const int col = wn * 64 + nt * 8 + (lane & 3) * 2;
            if (row0 < M)
                *(__half2*)(g_s1h + (size_t)row0 * F_HID + col) =
                    __floats2half2_rn(acc[mt][nt][0], acc[mt][nt][1]);
            if (row0 + 8 < M)
                *(__half2*)(g_s1h + (size_t)(row0 + 8) * F_HID + col) =
                    __floats2half2_rn(acc[mt][nt][2], acc[mt][nt][3]);
        }
    }
}

// ================= CSR build =================================================
__global__ void zero_cnt() {
    const int i = blockIdx.x * blockDim.x + threadIdx.x;
    if (i < N_NODES) g_cnt[i] = 0;
}

__global__ void hist_dst(const int* __restrict__ dst, int E) {
    const int e = blockIdx.x * blockDim.x + threadIdx.x;
    if (e < E) atomicAdd(&g_cnt[__ldcs(dst + e)], 1);
}

__global__ void scan_block() {
    __shared__ int sh[SCAN_B];
    const int t = threadIdx.x;
    const int i = blockIdx.x * SCAN_B + t;
    const int v = (i < N_NODES) ? g_cnt[i] : 0;
    sh[t] = v;
    __syncthreads();
    #pragma unroll
    for (int o = 1; o < SCAN_B; o <<= 1) {
        int x = 0;
        if (t >= o) x = sh[t - o];
        __syncthreads();
        sh[t] += x;
        __syncthreads();
    }
    if (i < N_NODES) g_off[i] = sh[t] - v;
    if (t == SCAN_B - 1) g_blksum[blockIdx.x] = sh[t];
}

__global__ void scan_top() {
    __shared__ int sh[256];
    const int t = threadIdx.x;
    const int v = (t < SCAN_NB) ? g_blksum[t] : 0;
    sh[t] = v;
    __syncthreads();
    #pragma unroll
    for (int o = 1; o < 256; o <<= 1) {
        int x = 0;
        if (t >= o) x = sh[t - o];
        __syncthreads();
        sh[t] += x;
        __syncthreads();
    }
    if (t < SCAN_NB) g_blksum[t] = sh[t] - v;
}

__global__ void scan_add() {
    const int i = blockIdx.x * blockDim.x + threadIdx.x;
    if (i < N_NODES) {
        const int o = g_off[i] + g_blksum[i / SCAN_B];
        g_off[i] = o;
        g_pos[i] = o;
    }
}

__global__ void fill_csr(const int* __restrict__ src, const int* __restrict__ dst,
                         const float* __restrict__ ew, int E) {
    const int e = blockIdx.x * blockDim.x + threadIdx.x;
    if (e < E) {
        const int p = atomicAdd(&g_pos[__ldcs(dst + e)], 1);
        __stcs(&g_csr[p], make_int2(__ldcs(src + e), __float_as_int(__ldcs(ew + e))));
    }
}

// ======== layer-1 gather: warp per node, full 256 feats (fp16 rows) =========
__device__ __forceinline__ void accum8(float* acc, uint4 v, float w) {
    const __half2* h = (const __half2*)&v;
    #pragma unroll
    for (int j = 0; j < 4; j++) {
        const float2 f = __half22float2(h[j]);
        acc[2 * j]     = fmaf(w, f.x, acc[2 * j]);
        acc[2 * j + 1] = fmaf(w, f.y, acc[2 * j + 1]);
    }
}

__global__ __launch_bounds__(256) void gather1(const float* __restrict__ b1,
                                               int base, int count) {
    const int i = (blockIdx.x * blockDim.x + threadIdx.x) >> 5;
    const int lane = threadIdx.x & 31;
    if (i >= count) return;
    const int n = base + i;
    const int beg = g_off[n];
    const int end = beg + g_cnt[n];

    float acc[8];
    {
        const float4 blo = __ldg((const float4*)b1 + lane * 2);
        const float4 bhi = __ldg((const float4*)b1 + lane * 2 + 1);
        acc[0] = blo.x; acc[1] = blo.y; acc[2] = blo.z; acc[3] = blo.w;
        acc[4] = bhi.x; acc[5] = bhi.y; acc[6] = bhi.z; acc[7] = bhi.w;
    }

    int e = beg;
    for (; e + 7 < end; e += 8) {
        int2 c[8];
        uint4 v[8];
        #pragma unroll
        for (int j = 0; j < 8; j++) c[j] = __ldcs(&g_csr[e + j]);
        #pragma unroll
        for (int j = 0; j < 8; j++)
            v[j] = __ldg((const uint4*)(g_s1h + (size_t)c[j].x * F_HID) + lane);
        #pragma unroll
        for (int j = 0; j < 8; j++) accum8(acc, v[j], __int_as_float(c[j].y));
    }
    for (; e < end; e++) {
        const int2 c = __ldcs(&g_csr[e]);
        const uint4 v = __ldg((const uint4*)(g_s1h + (size_t)c.x * F_HID) + lane);
        accum8(acc, v, __int_as_float(c.y));
    }

    uint4 o;
    __half2* ph = (__half2*)&o;
    #pragma unroll
    for (int j = 0; j < 4; j++)
        ph[j] = __floats2half2_rn(fmaxf(acc[2 * j], 0.f), fmaxf(acc[2 * j + 1], 0.f));
    __stcs((uint4*)(g_h1h + (size_t)n * F_HID) + lane, o);
}

// ====== gemm2: support2 = a1 @ W2 (fp16 mma; fragments from g_w2f) ==========
#define G2_NT 5
__global__ __launch_bounds__(256) void gemm2_mma(int base, int count) {
    const int tid = threadIdx.x;
    const int lane = tid & 31, warp = tid >> 5;
    const int i0 = blockIdx.x * 128 + warp * 16 + (lane >> 2);
    const int node0 = base + i0;
    const int node1 = node0 + 8;
    const bool v0 = i0 < count, v1 = (i0 + 8) < count;

    float acc[G2_NT][4];
    #pragma unroll
    for (int nt = 0; nt < G2_NT; nt++)
        #pragma unroll
        for (int r = 0; r < 4; r++) acc[nt][r] = 0.f;

    const __half* r0 = g_h1h + (size_t)node0 * F_HID;
    const __half* r1 = g_h1h + (size_t)node1 * F_HID;

    #pragma unroll
    for (int kt = 0; kt < 16; kt++) {
        const int kof = kt * 16 + (lane & 3) * 2;
        uint32_t a[4];
        a[0] = v0 ? __ldg((const uint32_t*)(r0 + kof))     : 0u;
        a[1] = v1 ? __ldg((const uint32_t*)(r1 + kof))     : 0u;
        a[2] = v0 ? __ldg((const uint32_t*)(r0 + kof + 8)) : 0u;
        a[3] = v1 ? __ldg((const uint32_t*)(r1 + kof + 8)) : 0u;
        #pragma unroll
        for (int nt = 0; nt < G2_NT; nt++) {
            const uint2 bv = __ldg((const uint2*)
                &g_w2f[(((size_t)kt * G2_NT + nt) * 32 + lane) * 2]);
            const uint32_t b[2] = {bv.x, bv.y};
            mma_f16(acc[nt], a, b);
        }
    }

    const int col = (lane & 3) * 2;
    #pragma unroll
    for (int nt = 0; nt < G2_NT; nt++) {
        if (v0)
            *(__half2*)(g_s2h + (size_t)node0 * F_OUT + nt * 8 + col) =
                __floats2half2_rn(acc[nt][0], acc[nt][1]);
        if (v1)
            *(__half2*)(g_s2h + (size_t)node1 * F_OUT + nt * 8 + col) =
                __floats2half2_rn(acc[nt][2], acc[nt][3]);
    }
}

// ========== layer-2 gather fused with log_softmax: warp per node ============
__global__ __launch_bounds__(256) void gather2_softmax(const float* __restrict__ b2,
                                                       float* __restrict__ out) {
    const int n = (blockIdx.x * blockDim.x + threadIdx.x) >> 5;
    const int lane = threadIdx.x & 31;
    if (n >= N_NODES) return;
    const int beg = g_off[n];
    const int end = beg + g_cnt[n];
    const bool act = lane < (F_OUT / 2);

    float accA = 0.f, accB = 0.f;
    if (act) {
        const float2 b = __ldg((const float2*)b2 + lane);
        accA = b.x; accB = b.y;
    }

    int e = beg;
    for (; e + 1 < end; e += 2) {
        const int2 c0 = __ldcs(&g_csr[e]);
        const int2 c1 = __ldcs(&g_csr[e + 1]);
        if (act) {
            const __half2 v0 = __ldg((const __half2*)(g_s2h + (size_t)c0.x * F_OUT) + lane);
            const __half2 v1 = __ldg((const __half2*)(g_s2h + (size_t)c1.x * F_OUT) + lane);
            const float w0 = __int_as_float(c0.y);
            const float w1 = __int_as_float(c1.y);
            const float2 f0 = __half22float2(v0);
            const float2 f1 = __half22float2(v1);
            accA = fmaf(w0, f0.x, accA); accB = fmaf(w0, f0.y, accB);
            accA = fmaf(w1, f1.x, accA); accB = fmaf(w1, f1.y, accB);
        }
    }
    if (e < end) {
        const int2 c = __ldcs(&g_csr[e]);
        if (act) {
            const __half2 v = __ldg((const __half2*)(g_s2h + (size_t)c.x * F_OUT) + lane);
            const float w = __int_as_float(c.y);
            const float2 f = __half22float2(v);
            accA = fmaf(w, f.x, accA); accB = fmaf(w, f.y, accB);
        }
    }

    const float NEG_INF = __int_as_float(0xff800000);
    float m = act ? fmaxf(accA, accB) : NEG_INF;
    #pragma unroll
    for (int o = 16; o > 0; o >>= 1)
        m = fmaxf(m, __shfl_xor_sync(0xffffffffu, m, o));
    float s = act ? (expf(accA - m) + expf(accB - m)) : 0.f;
    #pragma unroll
    for (int o = 16; o > 0; o >>= 1)
        s += __shfl_xor_sync(0xffffffffu, s, o);
    const float l = m + logf(s);

    if (act)
        *((float2*)(out + (size_t)n * F_OUT) + lane) = make_float2(accA - l, accB - l);
}

// ---------------- launch ----------------------------------------------------
extern "C" void kernel_launch(void* const* d_in, const int* in_sizes, int n_in,
                              void* d_out, int out_size) {
    const float* x   = (const float*)d_in[0];
    const int*   ei  = (const int*)d_in[1];
    const float* ew  = (const float*)d_in[2];
    const float* W1  = (const float*)d_in[3];
    const float* b1  = (const float*)d_in[4];
    const float* W2  = (const float*)d_in[5];
    const float* b2  = (const float*)d_in[6];
    float* out = (float*)d_out;

    const int E = in_sizes[2];
    const int* src = ei;
    const int* dst = ei + E;

    cudaStream_t s2;
    cudaStreamCreate(&s2);
    cudaEvent_t evFork, evJoin, evG1lo, evGemm2lo;
    cudaEventCreateWithFlags(&evFork, cudaEventDisableTiming);
    cudaEventCreateWithFlags(&evJoin, cudaEventDisableTiming);
    cudaEventCreateWithFlags(&evG1lo, cudaEventDisableTiming);
    cudaEventCreateWithFlags(&evGemm2lo, cudaEventDisableTiming);

    cudaEventRecord(evFork, 0);
    cudaStreamWaitEvent(s2, evFork, 0);

    // branch A (main stream): pack W1, then support1 = x @ W1
    pack_W1<<<128, 256>>>(W1);
    gemm1_f16<<<(N_NODES + G1_BM - 1) / G1_BM, 256>>>(x, N_NODES);

    // branch B (side stream): W2 pack + CSR build
    {
        const int nb = (N_NODES + 255) / 256;
        const int eb = (E + 255) / 256;
        pack_W2<<<10, 256, 0, s2>>>(W2);
        zero_cnt<<<nb, 256, 0, s2>>>();
        hist_dst<<<eb, 256, 0, s2>>>(dst, E);
        scan_block<<<SCAN_NB, SCAN_B, 0, s2>>>();
        scan_top<<<1, 256, 0, s2>>>();
        scan_add<<<nb, 256, 0, s2>>>();
        fill_csr<<<eb, 256, 0, s2>>>(src, dst, ew, E);
    }

    cudaEventRecord(evJoin, s2);
    cudaStreamWaitEvent(0, evJoin, 0);

    // pipelined layer-1 gather -> gemm2 (range-local dependency)
    gather1<<<(N_LO * 32 + 255) / 256, 256>>>(b1, 0, N_LO);
    cudaEventRecord(evG1lo, 0);
    cudaStreamWaitEvent(s2, evG1lo, 0);
    gemm2_mma<<<(N_LO + 127) / 128, 256, 0, s2>>>(0, N_LO);     // overlaps gather1_hi
    cudaEventRecord(evGemm2lo, s2);

    gather1<<<(N_HI * 32 + 255) / 256, 256>>>(b1, N_LO, N_HI);
    gemm2_mma<<<(N_HI + 127) / 128, 256>>>(N_LO, N_HI);
    cudaStreamWaitEvent(0, evGemm2lo, 0);

    // out = log_softmax(b2 + gather(ew * support2[src]))
    gather2_softmax<<<(N_NODES * 32 + 255) / 256, 256>>>(b2, out);

    cudaStreamDestroy(s2);
    cudaEventDestroy(evFork);
    cudaEventDestroy(evJoin);
    cudaEventDestroy(evG1lo);
    cudaEventDestroy(evGemm2lo);
}

// round 11
// speedup vs baseline: 1.0390x; 1.0332x over previous
#include <cuda_runtime.h>
#include <cuda_fp16.h>
#include <cstdint>

#define N_NODES 100000
#define F_IN    512
#define F_HID   256
#define F_OUT   40
#define E_MAX   3200000

#define SCAN_B  512
#define SCAN_NB ((N_NODES + SCAN_B - 1) / SCAN_B)   // 196

// ---------------- scratch (device globals; no allocation allowed) ----------
__device__ __align__(128) __half g_s1h[(size_t)N_NODES * F_HID];   // 51.2 MB
__device__ __align__(128) __half g_h1h[(size_t)N_NODES * F_HID];   // 51.2 MB
__device__ __align__(128) __half g_s2h[(size_t)N_NODES * F_OUT];   // 8 MB

// W1 pre-packed into mma B-fragment order: [kt(32)][nt(32)][lane(32)][2]
__device__ __align__(16) uint32_t g_w1f[32 * 32 * 32 * 2];          // 256 KB
// W2 pre-packed fragments: [kt(16)][nt(5)][lane(32)][2]
__device__ __align__(16) uint32_t g_w2f[16 * 5 * 32 * 2];           // 10 KB

__device__ int  g_cnt[N_NODES];
__device__ int  g_off[N_NODES];
__device__ int  g_pos[N_NODES];
__device__ int  g_blksum[SCAN_NB];
__device__ __align__(16) int2 g_csr[E_MAX];    // (src, float-bits of w)

// ---------------- fp16 mma helper -------------------------------------------
__device__ __forceinline__ void mma_f16(float* c, const uint32_t* a, const uint32_t* b) {
    asm volatile("mma.sync.aligned.m16n8k16.row.col.f32.f16.f16.f32 "
                 "{%0,%1,%2,%3}, {%4,%5,%6,%7}, {%8,%9}, {%0,%1,%2,%3};"
                 : "+f"(c[0]), "+f"(c[1]), "+f"(c[2]), "+f"(c[3])
                 : "r"(a[0]), "r"(a[1]), "r"(a[2]), "r"(a[3]),
                   "r"(b[0]), "r"(b[1]));
}

// ================ pack W1 (fp32 [512,256]) into fragment order ===============
__global__ void pack_W1(const float* __restrict__ W1) {
    const int idx = blockIdx.x * blockDim.x + threadIdx.x;   // 0..32767
    if (idx >= 32 * 32 * 32) return;
    const int kt = idx >> 10;
    const int rem = idx & 1023;
    const int nt = rem >> 5;
    const int ln = rem & 31;
    const int n = nt * 8 + (ln >> 2);
    const int k = kt * 16 + (ln & 3) * 2;
    const __half2 h0 = __floats2half2_rn(W1[(size_t)k * F_HID + n],
                                         W1[(size_t)(k + 1) * F_HID + n]);
    const __half2 h1 = __floats2half2_rn(W1[(size_t)(k + 8) * F_HID + n],
                                         W1[(size_t)(k + 9) * F_HID + n]);
    g_w1f[idx * 2]     = *(const uint32_t*)&h0;
    g_w1f[idx * 2 + 1] = *(const uint32_t*)&h1;
}

// ================ pack W2 (fp32 [256,40]) into fragment order ================
__global__ void pack_W2(const float* __restrict__ W2) {
    const int idx = blockIdx.x * blockDim.x + threadIdx.x;   // 0..2559
    if (idx >= 16 * 5 * 32) return;
    const int kt = idx / (5 * 32);
    const int rem = idx % (5 * 32);
    const int nt = rem / 32;
    const int ln = rem % 32;
    const int n = nt * 8 + (ln >> 2);
    const int k0 = kt * 16 + (ln & 3) * 2;
    const __half2 h0 = __floats2half2_rn(W2[(size_t)k0 * F_OUT + n],
                                         W2[(size_t)(k0 + 1) * F_OUT + n]);
    const __half2 h1 = __floats2half2_rn(W2[(size_t)(k0 + 8) * F_OUT + n],
                                         W2[(size_t)(k0 + 9) * F_OUT + n]);
    g_w2f[idx * 2]     = *(const uint32_t*)&h0;
    g_w2f[idx * 2 + 1] = *(const uint32_t*)&h1;
}

// ================= gemm1: support1 = x @ W1  (fp16 MMA, fp16 out) ==========
#define G1_BM 128
#define G1_BK 32
#define AS_PAD 36

__global__ __launch_bounds__(256, 1) void gemm1_f16(const float* __restrict__ A, int M) {
    __shared__ __align__(16) uint32_t As[2][8][8][AS_PAD];   // 18.4 KB

    const int tid  = threadIdx.x;
    const int lane = tid & 31;
    const int warp = tid >> 5;
    const int wm = warp & 1;
    const int wn = warp >> 1;
    const int rowBase = blockIdx.x * G1_BM;

    const int ar  = tid >> 1;
    const int aks = tid & 1;
    const int amt = ar >> 4, arr = ar & 15;
    const int b0  = arr >> 3;
    const int l0  = (arr & 7) * 4;

    float acc[4][8][4];
    #pragma unroll
    for (int mt = 0; mt < 4; mt++)
        #pragma unroll
        for (int nt = 0; nt < 8; nt++)
            #pragma unroll
            for (int r = 0; r < 4; r++) acc[mt][nt][r] = 0.f;

    const int arow = rowBase + ar;
    const float* Arow = A + (size_t)arow * F_IN + aks * 16;
    float4 pa[4];

    {
        #pragma unroll
        for (int j = 0; j < 4; j++)
            pa[j] = (arow < M) ? __ldcs((const float4*)(Arow + 4 * j))
                               : make_float4(0.f, 0.f, 0.f, 0.f);
        const float* f = (const float*)pa;
        uint4 lo, hi;
        uint32_t* plo = (uint32_t*)&lo;
        uint32_t* phi = (uint32_t*)&hi;
        #pragma unroll
        for (int p = 0; p < 4; p++) {
            const __half2 a = __floats2half2_rn(f[2 * p],     f[2 * p + 1]);
            const __half2 b = __floats2half2_rn(f[8 + 2 * p], f[9 + 2 * p]);
            plo[p] = *(const uint32_t*)&a;
            phi[p] = *(const uint32_t*)&b;
        }
        *(uint4*)&As[0][amt][aks * 4 + b0][l0]     = lo;
        *(uint4*)&As[0][amt][aks * 4 + b0 + 2][l0] = hi;
    }
    __syncthreads();

    const int NT = F_IN / G1_BK;   // 16
    for (int t = 0; t < NT; t++) {
        const int buf = t & 1;
        if (t + 1 < NT) {
            const float* Anext = Arow + (t + 1) * G1_BK;
            #pragma unroll
            for (int j = 0; j < 4; j++)
                pa[j] = (arow < M) ? __ldcs((const float4*)(Anext + 4 * j))
                                   : make_float4(0.f, 0.f, 0.f, 0.f);
        }

        #pragma unroll
        for (int ks = 0; ks < 2; ks++) {
            const int kt = t * 2 + ks;
            uint32_t bfr[8][2];
            #pragma unroll
            for (int nt = 0; nt < 8; nt++) {
                const uint2 v = __ldg((const uint2*)
                    &g_w1f[(((size_t)kt * 32 + wn * 8 + nt) * 32 + lane) * 2]);
                bfr[nt][0] = v.x; bfr[nt][1] = v.y;
            }
            uint32_t afr[4][4];
            #pragma unroll
            for (int mt = 0; mt < 4; mt++)
                #pragma unroll
                for (int r = 0; r < 4; r++)
                    afr[mt][r] = As[buf][wm * 4 + mt][ks * 4 + r][lane];
            #pragma unroll
            for (int mt = 0; mt < 4; mt++)
                #pragma unroll
                for (int nt = 0; nt < 8; nt++)
                    mma_f16(acc[mt][nt], afr[mt], bfr[nt]);
        }

        if (t + 1 < NT) {
            const int nb = buf ^ 1;
            const float* f = (const float*)pa;
            uint4 lo, hi;
            uint32_t* plo = (uint32_t*)&lo;
            uint32_t* phi = (uint32_t*)&hi;
            #pragma unroll
            for (int p = 0; p < 4; p++) {
                const __half2 a = __floats2half2_rn(f[2 * p],     f[2 * p + 1]);
                const __half2 b = __floats2half2_rn(f[8 + 2 * p], f[9 + 2 * p]);
                plo[p] = *(const uint32_t*)&a;
                phi[p] = *(const uint32_t*)&b;
            }
            *(uint4*)&As[nb][amt][aks * 4 + b0][l0]     = lo;
            *(uint4*)&As[nb][amt][aks * 4 + b0 + 2][l0] = hi;
        }
        __syncthreads();
    }

    #pragma unroll
    for (int mt = 0; mt < 4; mt++) {
        const int row0 = rowBase + wm * 64 + mt * 16 + (lane >> 2);
        #pragma unroll
        for (int nt = 0; nt < 8; nt++) {
            const int col = wn * 64 + nt * 8 + (lane & 3) * 2;
            if (row0 < M)
                *(__half2*)(g_s1h + (size_t)row0 * F_HID + col) =
                    __floats2half2_rn(acc[mt][nt][0], acc[mt][nt][1]);
            if (row0 + 8 < M)
                *(__half2*)(g_s1h + (size_t)(row0 + 8) * F_HID + col) =
                    __floats2half2_rn(acc[mt][nt][2], acc[mt][nt][3]);
        }
    }
}

// ================= CSR build =================================================
__global__ void zero_cnt() {
    const int i = blockIdx.x * blockDim.x + threadIdx.x;
    if (i < N_NODES) g_cnt[i] = 0;
}

__global__ void hist_dst(const int* __restrict__ dst, int E) {
    const int e = blockIdx.x * blockDim.x + threadIdx.x;
    if (e < E) atomicAdd(&g_cnt[__ldcs(dst + e)], 1);
}

__global__ void scan_block() {
    __shared__ int sh[SCAN_B];
    const int t = threadIdx.x;
    const int i = blockIdx.x * SCAN_B + t;
    const int v = (i < N_NODES) ? g_cnt[i] : 0;
    sh[t] = v;
    __syncthreads();
    #pragma unroll
    for (int o = 1; o < SCAN_B; o <<= 1) {
        int x = 0;
        if (t >= o) x = sh[t - o];
        __syncthreads();
        sh[t] += x;
        __syncthreads();
    }
    if (i < N_NODES) g_off[i] = sh[t] - v;
    if (t == SCAN_B - 1) g_blksum[blockIdx.x] = sh[t];
}

__global__ void scan_top() {
    __shared__ int sh[256];
    const int t = threadIdx.x;
    const int v = (t < SCAN_NB) ? g_blksum[t] : 0;
    sh[t] = v;
    __syncthreads();
    #pragma unroll
    for (int o = 1; o < 256; o <<= 1) {
        int x = 0;
        if (t >= o) x = sh[t - o];
        __syncthreads();
        sh[t] += x;
        __syncthreads();
    }
    if (t < SCAN_NB) g_blksum[t] = sh[t] - v;
}

__global__ void scan_add() {
    const int i = blockIdx.x * blockDim.x + threadIdx.x;
    if (i < N_NODES) {
        const int o = g_off[i] + g_blksum[i / SCAN_B];
        g_off[i] = o;
        g_pos[i] = o;
    }
}

__global__ void fill_csr(const int* __restrict__ src, const int* __restrict__ dst,
                         const float* __restrict__ ew, int E) {
    const int e = blockIdx.x * blockDim.x + threadIdx.x;
    if (e < E) {
        const int p = atomicAdd(&g_pos[__ldcs(dst + e)], 1);
        __stcs(&g_csr[p], make_int2(__ldcs(src + e), __float_as_int(__ldcs(ew + e))));
    }
}

// ======== layer-1 gather: warp per node, full 256 feats (fp16 rows) =========
__device__ __forceinline__ void accum8(float* acc, uint4 v, float w) {
    const __half2* h = (const __half2*)&v;
    #pragma unroll
    for (int j = 0; j < 4; j++) {
        const float2 f = __half22float2(h[j]);
        acc[2 * j]     = fmaf(w, f.x, acc[2 * j]);
        acc[2 * j + 1] = fmaf(w, f.y, acc[2 * j + 1]);
    }
}

__global__ __launch_bounds__(256) void gather1(const float* __restrict__ b1) {
    const int n = (blockIdx.x * blockDim.x + threadIdx.x) >> 5;
    const int lane = threadIdx.x & 31;
    if (n >= N_NODES) return;
    const int beg = g_off[n];
    const int end = beg + g_cnt[n];

    float acc[8];
    {
        const float4 blo = __ldg((const float4*)b1 + lane * 2);
        const float4 bhi = __ldg((const float4*)b1 + lane * 2 + 1);
        acc[0] = blo.x; acc[1] = blo.y; acc[2] = blo.z; acc[3] = blo.w;
        acc[4] = bhi.x; acc[5] = bhi.y; acc[6] = bhi.z; acc[7] = bhi.w;
    }

    int e = beg;
    for (; e + 7 < end; e += 8) {
        int2 c[8];
        uint4 v[8];
        #pragma unroll
        for (int i = 0; i < 8; i++) c[i] = __ldcs(&g_csr[e + i]);
        #pragma unroll
        for (int i = 0; i < 8; i++)
            v[i] = __ldg((const uint4*)(g_s1h + (size_t)c[i].x * F_HID) + lane);
        #pragma unroll
        for (int i = 0; i < 8; i++) accum8(acc, v[i], __int_as_float(c[i].y));
    }
    for (; e < end; e++) {
        const int2 c = __ldcs(&g_csr[e]);
        const uint4 v = __ldg((const uint4*)(g_s1h + (size_t)c.x * F_HID) + lane);
        accum8(acc, v, __int_as_float(c.y));
    }

    uint4 o;
    __half2* ph = (__half2*)&o;
    #pragma unroll
    for (int j = 0; j < 4; j++)
        ph[j] = __floats2half2_rn(fmaxf(acc[2 * j], 0.f), fmaxf(acc[2 * j + 1], 0.f));
    __stcs((uint4*)(g_h1h + (size_t)n * F_HID) + lane, o);
}

// ====== gemm2: support2 = a1 @ W2 (fp16 mma; fragments from g_w2f) ==========
#define G2_NT 5
__global__ __launch_bounds__(256) void gemm2_mma() {
    const int tid = threadIdx.x;
    const int lane = tid & 31, warp = tid >> 5;
    const int node0 = blockIdx.x * 128 + warp * 16 + (lane >> 2);
    const int node1 = node0 + 8;
    const bool v0 = node0 < N_NODES, v1 = node1 < N_NODES;

    float acc[G2_NT][4];
    #pragma unroll
    for (int nt = 0; nt < G2_NT; nt++)
        #pragma unroll
        for (int r = 0; r < 4; r++) acc[nt][r] = 0.f;

    const __half* r0 = g_h1h + (size_t)node0 * F_HID;
    const __half* r1 = g_h1h + (size_t)node1 * F_HID;

    #pragma unroll
    for (int kt = 0; kt < 16; kt++) {
        const int kof = kt * 16 + (lane & 3) * 2;
        uint32_t a[4];
        a[0] = v0 ? __ldg((const uint32_t*)(r0 + kof))     : 0u;
        a[1] = v1 ? __ldg((const uint32_t*)(r1 + kof))     : 0u;
        a[2] = v0 ? __ldg((const uint32_t*)(r0 + kof + 8)) : 0u;
        a[3] = v1 ? __ldg((const uint32_t*)(r1 + kof + 8)) : 0u;
        #pragma unroll
        for (int nt = 0; nt < G2_NT; nt++) {
            const uint2 bv = __ldg((const uint2*)
                &g_w2f[(((size_t)kt * G2_NT + nt) * 32 + lane) * 2]);
            const uint32_t b[2] = {bv.x, bv.y};
            mma_f16(acc[nt], a, b);
        }
    }

    const int col = (lane & 3) * 2;
    #pragma unroll
    for (int nt = 0; nt < G2_NT; nt++) {
        if (v0)
            *(__half2*)(g_s2h + (size_t)node0 * F_OUT + nt * 8 + col) =
                __floats2half2_rn(acc[nt][0], acc[nt][1]);
        if (v1)
            *(__half2*)(g_s2h + (size_t)node1 * F_OUT + nt * 8 + col) =
                __floats2half2_rn(acc[nt][2], acc[nt][3]);
    }
}

// ========== layer-2 gather fused with log_softmax: warp per node ============
__global__ __launch_bounds__(256) void gather2_softmax(const float* __restrict__ b2,
                                                       float* __restrict__ out) {
    const int n = (blockIdx.x * blockDim.x + threadIdx.x) >> 5;
    const int lane = threadIdx.x & 31;
    if (n >= N_NODES) return;
    const int beg = g_off[n];
    const int end = beg + g_cnt[n];
    const bool act = lane < (F_OUT / 2);

    float accA = 0.f, accB = 0.f;
    if (act) {
        const float2 b = __ldg((const float2*)b2 + lane);
        accA = b.x; accB = b.y;
    }

    int e = beg;
    for (; e + 1 < end; e += 2) {
        const int2 c0 = __ldcs(&g_csr[e]);
        const int2 c1 = __ldcs(&g_csr[e + 1]);
        if (act) {
            const __half2 v0 = __ldg((const __half2*)(g_s2h + (size_t)c0.x * F_OUT) + lane);
            const __half2 v1 = __ldg((const __half2*)(g_s2h + (size_t)c1.x * F_OUT) + lane);
            const float w0 = __int_as_float(c0.y);
            const float w1 = __int_as_float(c1.y);
            const float2 f0 = __half22float2(v0);
            const float2 f1 = __half22float2(v1);
            accA = fmaf(w0, f0.x, accA); accB = fmaf(w0, f0.y, accB);
            accA = fmaf(w1, f1.x, accA); accB = fmaf(w1, f1.y, accB);
        }
    }
    if (e < end) {
        const int2 c = __ldcs(&g_csr[e]);
        if (act) {
            const __half2 v = __ldg((const __half2*)(g_s2h + (size_t)c.x * F_OUT) + lane);
            const float w = __int_as_float(c.y);
            const float2 f = __half22float2(v);
            accA = fmaf(w, f.x, accA); accB = fmaf(w, f.y, accB);
        }
    }

    const float NEG_INF = __int_as_float(0xff800000);
    float m = act ? fmaxf(accA, accB) : NEG_INF;
    #pragma unroll
    for (int o = 16; o > 0; o >>= 1)
        m = fmaxf(m, __shfl_xor_sync(0xffffffffu, m, o));
    float s = act ? (expf(accA - m) + expf(accB - m)) : 0.f;
    #pragma unroll
    for (int o = 16; o > 0; o >>= 1)
        s += __shfl_xor_sync(0xffffffffu, s, o);
    const float l = m + logf(s);

    if (act)
        *((float2*)(out + (size_t)n * F_OUT) + lane) = make_float2(accA - l, accB - l);
}

// ---------------- launch ----------------------------------------------------
extern "C" void kernel_launch(void* const* d_in, const int* in_sizes, int n_in,
                              void* d_out, int out_size) {
    const float* x   = (const float*)d_in[0];
    const int*   ei  = (const int*)d_in[1];
    const float* ew  = (const float*)d_in[2];
    const float* W1  = (const float*)d_in[3];
    const float* b1  = (const float*)d_in[4];
    const float* W2  = (const float*)d_in[5];
    const float* b2  = (const float*)d_in[6];
    float* out = (float*)d_out;

    const int E = in_sizes[2];
    const int* src = ei;
    const int* dst = ei + E;

    // Fork: CSR build + W2 pack run concurrently with W1 pack + gemm1.
    cudaStream_t s2;
    cudaStreamCreate(&s2);
    cudaEvent_t evFork, evJoin;
    cudaEventCreateWithFlags(&evFork, cudaEventDisableTiming);
    cudaEventCreateWithFlags(&evJoin, cudaEventDisableTiming);

    cudaEventRecord(evFork, 0);
    cudaStreamWaitEvent(s2, evFork, 0);

    // branch A (main stream): pack W1, then support1 = x @ W1
    pack_W1<<<128, 256>>>(W1);
    gemm1_f16<<<(N_NODES + G1_BM - 1) / G1_BM, 256>>>(x, N_NODES);

    // branch B (side stream): W2 pack + CSR build
    {
        const int nb = (N_NODES + 255) / 256;
        const int eb = (E + 255) / 256;
        pack_W2<<<10, 256, 0, s2>>>(W2);
        zero_cnt<<<nb, 256, 0, s2>>>();
        hist_dst<<<eb, 256, 0, s2>>>(dst, E);
        scan_block<<<SCAN_NB, SCAN_B, 0, s2>>>();
        scan_top<<<1, 256, 0, s2>>>();
        scan_add<<<nb, 256, 0, s2>>>();
        fill_csr<<<eb, 256, 0, s2>>>(src, dst, ew, E);
    }

    cudaEventRecord(evJoin, s2);
    cudaStreamWaitEvent(0, evJoin, 0);

    // layer-1 gather + relu + fp16 store
    gather1<<<(N_NODES * 32 + 255) / 256, 256>>>(b1);
    // support2 = a1 @ W2  (fp16 mma, fragments from gmem)
    gemm2_mma<<<(N_NODES + 127) / 128, 256>>>();
    // out = log_softmax(b2 + gather(ew * support2[src]))
    gather2_softmax<<<(N_NODES * 32 + 255) / 256, 256>>>(b2, out);

    cudaStreamDestroy(s2);
    cudaEventDestroy(evFork);
    cudaEventDestroy(evJoin);
}